// round 6
// baseline (speedup 1.0000x reference)
#include <cuda_runtime.h>
#include <math.h>
#include <cstdint>

#define B_  64
#define T_  2048
#define I_  128
#define H_  256

#define NG 16      // batch groups
#define NS 8       // hidden slices per group
#define NB 4       // batches per group
#define NU 32      // hidden units per slice
#define THREADS 256

#define WXSTRIDE 132   // %32==4 -> conflict-free LDS.128 weight rows

// ---- SMEM layout (float offsets) ----
#define OFF_WX   0
#define SZ_WX    (3*32*WXSTRIDE)           // 12672
#define OFF_BR   (OFF_WX + SZ_WX)
#define OFF_BZ   (OFF_BR + 32)
#define OFF_BIN  (OFF_BZ + 32)
#define OFF_BHN  (OFF_BIN + 32)
#define OFF_X    (OFF_BHN + 32)            // 2 x [b][128] = 1024
#define OFF_H    (OFF_X + 1024)            // 2 x [b][256] = 2048
#define OFF_PX   (OFF_H + 2048)            // 2 x [g][b][chunk4][u] = 3072
#define OFF_PH   (OFF_PX + 3072)           // [g][b][chunk8][u] = 3072
#define SMEM_FLOATS (OFF_PH + 3072)
#define SMEM_BYTES  (SMEM_FLOATS * 4)      // ~88 KB

typedef unsigned long long ull;

// flags[grp][b][slc] : value v means "h_{v-1} for (grp,b) slice slc is visible"
#define NFLAGS (NG * NB * NS)
__device__ unsigned g_flags2[NFLAGS];      // zero-init; reset by out kernel for graph replay

__device__ __forceinline__ uint32_t smem_u32(const void* p) {
    uint32_t a;
    asm("{ .reg .u64 t; cvta.to.shared.u64 t, %1; cvt.u32.u64 %0, t; }" : "=r"(a) : "l"(p));
    return a;
}
__device__ __forceinline__ unsigned ld_acquire(const unsigned* p) {
    unsigned v;
    asm volatile("ld.global.acquire.gpu.u32 %0, [%1];" : "=r"(v) : "l"(p) : "memory");
    return v;
}
__device__ __forceinline__ void st_release(unsigned* p, unsigned v) {
    asm volatile("st.release.gpu.global.u32 [%0], %1;" :: "l"(p), "r"(v) : "memory");
}
#define FFMA2(d, a, b) \
    asm volatile("fma.rn.f32x2 %0, %1, %2, %0;" : "+l"(d) : "l"(a), "l"(b))

__device__ __forceinline__ float psum(ull v) {
    unsigned lo, hi;
    asm("mov.b64 {%0,%1}, %2;" : "=r"(lo), "=r"(hi) : "l"(v));
    return __uint_as_float(lo) + __uint_as_float(hi);
}
__device__ __forceinline__ ull packf2(float a, float b) {
    ull w;
    asm("mov.b64 %0, {%1,%2};" : "=l"(w) : "r"(__float_as_uint(a)), "r"(__float_as_uint(b)));
    return w;
}

__global__ void __launch_bounds__(THREADS, 1)
gru_scan_kernel(const float* __restrict__ x,
                const float* __restrict__ Wih,
                const float* __restrict__ Whh,
                const float* __restrict__ bih,
                const float* __restrict__ bhh,
                float* __restrict__ outbuf)
{
    extern __shared__ float smem[];
    const int tid = threadIdx.x;
    const int cta = blockIdx.x;
    const int grp = cta >> 3;
    const int slc = cta & 7;
    const int b0  = grp * NB;
    const int u0  = slc * NU;
    const uint32_t sbase = smem_u32(smem);

    float* hid = outbuf + (size_t)B_ * T_;   // hiddens [B][T][H]

    const int wid = tid >> 5;
    const int u   = tid & 31;
    const int kw  = wid * 32;                // this warp's K-chunk of W_hh

    // ---- one-time: W_ih slice into SMEM [g][u][k] (stride WXSTRIDE) ----
    for (int rk = tid; rk < 96 * 128; rk += THREADS) {
        int row = rk >> 7;
        int k   = rk & 127;
        int g   = row >> 5;
        int uu  = row & 31;
        smem[OFF_WX + (g * 32 + uu) * WXSTRIDE + k] =
            Wih[(size_t)(g * 256 + u0 + uu) * I_ + k];
    }
    if (tid < 32) {
        int uu = tid;
        smem[OFF_BR  + uu] = bih[0 * 256 + u0 + uu] + bhh[0 * 256 + u0 + uu];
        smem[OFF_BZ  + uu] = bih[1 * 256 + u0 + uu] + bhh[1 * 256 + u0 + uu];
        smem[OFF_BIN + uu] = bih[2 * 256 + u0 + uu];
        smem[OFF_BHN + uu] = bhh[2 * 256 + u0 + uu];
    }
    // preload x_0 into buffer 0: layout [b][k]
    for (int e = tid; e < 512; e += THREADS) {
        int b = e >> 7, k = e & 127;
        smem[OFF_X + e] = x[((size_t)(b0 + b) * T_ + 0) * I_ + k];
    }

    // ---- one-time: W_hh into REGISTERS ----
    ull wh[48];
    #pragma unroll
    for (int g = 0; g < 3; ++g) {
        const float* row = Whh + (size_t)(g * 256 + u0 + u) * H_ + kw;
        #pragma unroll
        for (int j = 0; j < 16; ++j) {
            float2 v = *reinterpret_cast<const float2*>(row + 2 * j);
            wh[g * 16 + j] = packf2(v.x, v.y);
        }
    }
    __syncthreads();

    // per-lane x-weight row bases (gates)
    const float* wx0 = smem + OFF_WX + (0 * 32 + u) * WXSTRIDE;
    const float* wx1 = smem + OFF_WX + (1 * 32 + u) * WXSTRIDE;
    const float* wx2 = smem + OFF_WX + (2 * 32 + u) * WXSTRIDE;

    for (int t = 0; t < T_; ++t) {
        const int p = t & 1;
        const int q = p ^ 1;

        if (wid < 4) {
            // ---- prefetch x_{t+1} ----
            if (t + 1 < T_) {
                int b = wid, c = u;
                uint32_t dst = sbase + (OFF_X + q * 512 + b * 128 + c * 4) * 4;
                const float* src = x + ((size_t)(b0 + b) * T_ + (t + 1)) * I_ + c * 4;
                asm volatile("cp.async.cg.shared.global [%0], [%1], 16;" :: "r"(dst), "l"(src));
                asm volatile("cp.async.commit_group;" ::: "memory");
            }
            // ---- x-GEMM: warp covers k in [wid*32, wid*32+32) ----
            ull acc[12];
            #pragma unroll
            for (int i = 0; i < 12; ++i) acc[i] = 0ull;

            const float* xq = smem + OFF_X + p * 512;
            const int kx = wid * 32;
            #pragma unroll
            for (int j = 0; j < 8; ++j) {
                const int k = kx + 4 * j;
                ulonglong2 xv0 = *reinterpret_cast<const ulonglong2*>(xq + 0 * 128 + k);
                ulonglong2 xv1 = *reinterpret_cast<const ulonglong2*>(xq + 1 * 128 + k);
                ulonglong2 xv2 = *reinterpret_cast<const ulonglong2*>(xq + 2 * 128 + k);
                ulonglong2 xv3 = *reinterpret_cast<const ulonglong2*>(xq + 3 * 128 + k);
                ulonglong2 w0 = *reinterpret_cast<const ulonglong2*>(wx0 + k);
                ulonglong2 w1 = *reinterpret_cast<const ulonglong2*>(wx1 + k);
                ulonglong2 w2 = *reinterpret_cast<const ulonglong2*>(wx2 + k);
                FFMA2(acc[0], w0.x, xv0.x); FFMA2(acc[0], w0.y, xv0.y);
                FFMA2(acc[1], w0.x, xv1.x); FFMA2(acc[1], w0.y, xv1.y);
                FFMA2(acc[2], w0.x, xv2.x); FFMA2(acc[2], w0.y, xv2.y);
                FFMA2(acc[3], w0.x, xv3.x); FFMA2(acc[3], w0.y, xv3.y);
                FFMA2(acc[4], w1.x, xv0.x); FFMA2(acc[4], w1.y, xv0.y);
                FFMA2(acc[5], w1.x, xv1.x); FFMA2(acc[5], w1.y, xv1.y);
                FFMA2(acc[6], w1.x, xv2.x); FFMA2(acc[6], w1.y, xv2.y);
                FFMA2(acc[7], w1.x, xv3.x); FFMA2(acc[7], w1.y, xv3.y);
                FFMA2(acc[8], w2.x, xv0.x); FFMA2(acc[8], w2.y, xv0.y);
                FFMA2(acc[9], w2.x, xv1.x); FFMA2(acc[9], w2.y, xv1.y);
                FFMA2(acc[10], w2.x, xv2.x); FFMA2(acc[10], w2.y, xv2.y);
                FFMA2(acc[11], w2.x, xv3.x); FFMA2(acc[11], w2.y, xv3.y);
            }
            float* px = smem + OFF_PX + p * 1536;
            #pragma unroll
            for (int g = 0; g < 3; ++g)
                #pragma unroll
                for (int b = 0; b < 4; ++b)
                    px[((g * 4 + b) * 4 + wid) * 32 + u] = psum(acc[g * 4 + b]);

            if (t + 1 < T_)
                asm volatile("cp.async.wait_group 0;" ::: "memory");
        } else {
            // ---- per-batch poll (warp = batch): wait for THIS batch's 8 slice flags ----
            if (t > 0) {
                const int b = wid - 4;
                const unsigned* fp = &g_flags2[(grp * NB + b) * NS];
                const unsigned tgt = (unsigned)t;
                for (;;) {
                    unsigned v = ld_acquire(fp + (u & 7));   // 32B sector, coalesced
                    if (__all_sync(0xffffffffu, v >= tgt)) break;
                }
                // load h_{t-1} for our batch (published by the 8 slices)
                const float* src = &hid[((size_t)(b0 + b) * T_ + (t - 1)) * H_];
                float4 v0 = *reinterpret_cast<const float4*>(src + u * 4);
                float4 v1 = *reinterpret_cast<const float4*>(src + 128 + u * 4);
                *reinterpret_cast<float4*>(&smem[OFF_H + p * 1024 + b * 256 + u * 4]) = v0;
                *reinterpret_cast<float4*>(&smem[OFF_H + p * 1024 + b * 256 + 128 + u * 4]) = v1;
            }
        }
        __syncthreads();   // (A) sH ready; x_{t+1} landed

        // ---- h-GEMM: all 8 warps, weights from registers ----
        if (t > 0) {
            ull acc[12];
            #pragma unroll
            for (int i = 0; i < 12; ++i) acc[i] = 0ull;

            const float* hq = smem + OFF_H + p * 1024;
            #pragma unroll
            for (int jj = 0; jj < 8; ++jj) {
                const int k = kw + 4 * jj;
                ulonglong2 h0 = *reinterpret_cast<const ulonglong2*>(hq + 0 * 256 + k);
                ulonglong2 h1 = *reinterpret_cast<const ulonglong2*>(hq + 1 * 256 + k);
                ulonglong2 h2 = *reinterpret_cast<const ulonglong2*>(hq + 2 * 256 + k);
                ulonglong2 h3 = *reinterpret_cast<const ulonglong2*>(hq + 3 * 256 + k);
                #pragma unroll
                for (int g = 0; g < 3; ++g) {
                    const ull wa = wh[g * 16 + 2 * jj];
                    const ull wb = wh[g * 16 + 2 * jj + 1];
                    FFMA2(acc[g * 4 + 0], wa, h0.x); FFMA2(acc[g * 4 + 0], wb, h0.y);
                    FFMA2(acc[g * 4 + 1], wa, h1.x); FFMA2(acc[g * 4 + 1], wb, h1.y);
                    FFMA2(acc[g * 4 + 2], wa, h2.x); FFMA2(acc[g * 4 + 2], wb, h2.y);
                    FFMA2(acc[g * 4 + 3], wa, h3.x); FFMA2(acc[g * 4 + 3], wb, h3.y);
                }
            }
            float* ph = smem + OFF_PH;
            #pragma unroll
            for (int g = 0; g < 3; ++g)
                #pragma unroll
                for (int b = 0; b < 4; ++b)
                    ph[((g * 4 + b) * 8 + wid) * 32 + u] = psum(acc[g * 4 + b]);
        }
        __syncthreads();   // (B) sPh visible

        // ---- combine + per-warp publish: warps 0-3 (warp = batch, lane = unit) ----
        if (wid < 4) {
            const int bb = wid, uu = u;
            const float* px = smem + OFF_PX + p * 1536;
            float sx0 = 0.f, sx1 = 0.f, sx2 = 0.f;
            #pragma unroll
            for (int c = 0; c < 4; ++c) {
                sx0 += px[((0 * 4 + bb) * 4 + c) * 32 + uu];
                sx1 += px[((1 * 4 + bb) * 4 + c) * 32 + uu];
                sx2 += px[((2 * 4 + bb) * 4 + c) * 32 + uu];
            }
            float sh0 = 0.f, sh1 = 0.f, sh2 = 0.f, hprev = 0.f;
            if (t > 0) {
                const float* ph = smem + OFF_PH;
                #pragma unroll
                for (int c = 0; c < 8; ++c) {
                    sh0 += ph[((0 * 4 + bb) * 8 + c) * 32 + uu];
                    sh1 += ph[((1 * 4 + bb) * 8 + c) * 32 + uu];
                    sh2 += ph[((2 * 4 + bb) * 8 + c) * 32 + uu];
                }
                hprev = smem[OFF_H + p * 1024 + bb * 256 + u0 + uu];
            }
            const float pre_r = sx0 + sh0 + smem[OFF_BR + uu];
            const float pre_z = sx1 + sh1 + smem[OFF_BZ + uu];
            const float r = __fdividef(1.f, 1.f + __expf(-pre_r));
            const float z = __fdividef(1.f, 1.f + __expf(-pre_z));
            const float v = (sx2 + smem[OFF_BIN + uu]) + r * (sh2 + smem[OFF_BHN + uu]);
            const float nn = 1.f - __fdividef(2.f, __expf(2.f * v) + 1.f);   // tanh(v)
            const float hnew = (1.f - z) * nn + z * hprev;

            hid[((size_t)(b0 + bb) * T_ + t) * H_ + u0 + uu] = hnew;

            __syncwarp();   // all 32 h-stores of this warp precede the release
            if (uu == 0)
                st_release(&g_flags2[(grp * NB + bb) * NS + slc], (unsigned)(t + 1));
        }
        // no trailing syncthreads: buffer parity + flag backpressure make reuse safe
    }
}

// outputs[b,t] = hiddens[b,t,:] . W_o + b_o ; resets flags for graph replay
__global__ void gru_out_kernel(const float* __restrict__ Wo,
                               const float* __restrict__ bo,
                               float* __restrict__ outbuf)
{
    if (blockIdx.x == 0) {
        for (int i = threadIdx.x; i < NFLAGS; i += blockDim.x)
            g_flags2[i] = 0u;
    }

    int gw   = (int)((blockIdx.x * blockDim.x + threadIdx.x) >> 5);
    int lane = threadIdx.x & 31;
    if (gw >= B_ * T_) return;

    const float* hrow = outbuf + (size_t)B_ * T_ + (size_t)gw * H_;
    float s = 0.f;
    #pragma unroll
    for (int c = 0; c < 8; ++c) {
        int k = c * 32 + lane;
        s += hrow[k] * __ldg(&Wo[k]);
    }
    #pragma unroll
    for (int off = 16; off; off >>= 1)
        s += __shfl_xor_sync(0xffffffffu, s, off);
    if (lane == 0) outbuf[gw] = s + __ldg(&bo[0]);
}

extern "C" void kernel_launch(void* const* d_in, const int* in_sizes, int n_in,
                              void* d_out, int out_size)
{
    const float* x   = (const float*)d_in[0];
    const float* Wih = (const float*)d_in[1];
    const float* Whh = (const float*)d_in[2];
    const float* bih = (const float*)d_in[3];
    const float* bhh = (const float*)d_in[4];
    const float* Wo  = (const float*)d_in[5];
    const float* bo  = (const float*)d_in[6];
    float* out = (float*)d_out;

    cudaFuncSetAttribute(gru_scan_kernel,
                         cudaFuncAttributeMaxDynamicSharedMemorySize, SMEM_BYTES);

    gru_scan_kernel<<<NG * NS, THREADS, SMEM_BYTES>>>(x, Wih, Whh, bih, bhh, out);
    gru_out_kernel<<<(B_ * T_ * 32) / 256, 256>>>(Wo, bo, out);
}

// round 7
// speedup vs baseline: 1.4693x; 1.4693x over previous
#include <cuda_runtime.h>
#include <math.h>
#include <cstdint>

#define B_  64
#define T_  2048
#define I_  128
#define H_  256

#define NG 16      // batch groups
#define NS 8       // hidden slices per group
#define NB 4       // batches per group (2 pairs of 2)
#define NU 32      // hidden units per slice
#define THREADS 256
#define WXSTRIDE 132   // %32==4 -> conflict-free LDS.128 weight rows

// ---- SMEM layout (float offsets) ----
#define OFF_WX   0
#define SZ_WX    (3*32*WXSTRIDE)           // 12672
#define OFF_BR   (OFF_WX + SZ_WX)
#define OFF_BZ   (OFF_BR + 32)
#define OFF_BIN  (OFF_BZ + 32)
#define OFF_BHN  (OFF_BIN + 32)
#define OFF_X    (OFF_BHN + 32)            // [pair][parity][b2][128] = 1024
#define OFF_H    (OFF_X + 1024)            // [pair][b2][256] = 1024
#define OFF_PX   (OFF_H + 1024)            // [pair][g3][b2][chunk4][u32] = 1536
#define OFF_PH   (OFF_PX + 1536)           // [g3][b2][chunk8][u32] = 1536
#define SMEM_FLOATS (OFF_PH + 1536)
#define SMEM_BYTES  (SMEM_FLOATS * 4)      // ~70 KB

typedef unsigned long long ull;

// one flag per (group, pair), each in its own 32B sector
#define NFLAGW (NG * 2 * 8)
__device__ unsigned g_flagsP[NFLAGW];      // zero-init; reset by out kernel for graph replay

__device__ __forceinline__ uint32_t smem_u32(const void* p) {
    uint32_t a;
    asm("{ .reg .u64 t; cvta.to.shared.u64 t, %1; cvt.u32.u64 %0, t; }" : "=r"(a) : "l"(p));
    return a;
}
__device__ __forceinline__ unsigned ld_acquire(const unsigned* p) {
    unsigned v;
    asm volatile("ld.global.acquire.gpu.u32 %0, [%1];" : "=r"(v) : "l"(p) : "memory");
    return v;
}
__device__ __forceinline__ void red_release_add(unsigned* p, unsigned v) {
    asm volatile("red.release.gpu.global.add.u32 [%0], %1;" :: "l"(p), "r"(v) : "memory");
}
#define FFMA2(d, a, b) \
    asm volatile("fma.rn.f32x2 %0, %1, %2, %0;" : "+l"(d) : "l"(a), "l"(b))

__device__ __forceinline__ float psum(ull v) {
    unsigned lo, hi;
    asm("mov.b64 {%0,%1}, %2;" : "=r"(lo), "=r"(hi) : "l"(v));
    return __uint_as_float(lo) + __uint_as_float(hi);
}
__device__ __forceinline__ ull packf2(float a, float b) {
    ull w;
    asm("mov.b64 %0, {%1,%2};" : "=l"(w) : "r"(__float_as_uint(a)), "r"(__float_as_uint(b)));
    return w;
}

// x-GEMM for (pair Ptgt, time ttgt): warps 2-5 (ch = wid-2), writes PX[Ptgt]
__device__ __forceinline__ void xgemm_pair(float* smem,
                                           const float* wx0, const float* wx1, const float* wx2,
                                           int ch, int u, int Ptgt, int ttgt)
{
    ull acc[6];
    #pragma unroll
    for (int i = 0; i < 6; ++i) acc[i] = 0ull;
    const float* xq = smem + OFF_X + (Ptgt * 2 + (ttgt & 1)) * 256;
    const int kx = ch * 32;
    #pragma unroll
    for (int j = 0; j < 8; ++j) {
        const int k = kx + 4 * j;
        ulonglong2 x0 = *reinterpret_cast<const ulonglong2*>(xq + k);
        ulonglong2 x1 = *reinterpret_cast<const ulonglong2*>(xq + 128 + k);
        ulonglong2 w0 = *reinterpret_cast<const ulonglong2*>(wx0 + k);
        ulonglong2 w1 = *reinterpret_cast<const ulonglong2*>(wx1 + k);
        ulonglong2 w2 = *reinterpret_cast<const ulonglong2*>(wx2 + k);
        FFMA2(acc[0], w0.x, x0.x); FFMA2(acc[0], w0.y, x0.y);
        FFMA2(acc[1], w0.x, x1.x); FFMA2(acc[1], w0.y, x1.y);
        FFMA2(acc[2], w1.x, x0.x); FFMA2(acc[2], w1.y, x0.y);
        FFMA2(acc[3], w1.x, x1.x); FFMA2(acc[3], w1.y, x1.y);
        FFMA2(acc[4], w2.x, x0.x); FFMA2(acc[4], w2.y, x0.y);
        FFMA2(acc[5], w2.x, x1.x); FFMA2(acc[5], w2.y, x1.y);
    }
    float* px = smem + OFF_PX + Ptgt * 768;
    #pragma unroll
    for (int g = 0; g < 3; ++g)
        #pragma unroll
        for (int b = 0; b < 2; ++b)
            px[((g * 2 + b) * 4 + ch) * 32 + u] = psum(acc[g * 2 + b]);
}

__global__ void __launch_bounds__(THREADS, 1)
gru_scan_kernel(const float* __restrict__ x,
                const float* __restrict__ Wih,
                const float* __restrict__ Whh,
                const float* __restrict__ bih,
                const float* __restrict__ bhh,
                float* __restrict__ outbuf)
{
    extern __shared__ float smem[];
    const int tid = threadIdx.x;
    const int cta = blockIdx.x;
    const int grp = cta >> 3;
    const int slc = cta & 7;
    const int b0  = grp * NB;
    const int u0  = slc * NU;
    const uint32_t sbase = smem_u32(smem);

    float* hid = outbuf + (size_t)B_ * T_;   // hiddens [B][T][H]

    const int wid = tid >> 5;
    const int u   = tid & 31;
    const int kw  = wid * 32;                // this warp's K-chunk of W_hh

    // ---- one-time: W_ih slice into SMEM [g][u][k] (stride WXSTRIDE) ----
    for (int rk = tid; rk < 96 * 128; rk += THREADS) {
        int row = rk >> 7;
        int k   = rk & 127;
        int g   = row >> 5;
        int uu  = row & 31;
        smem[OFF_WX + (g * 32 + uu) * WXSTRIDE + k] =
            Wih[(size_t)(g * 256 + u0 + uu) * I_ + k];
    }
    if (tid < 32) {
        int uu = tid;
        smem[OFF_BR  + uu] = bih[0 * 256 + u0 + uu] + bhh[0 * 256 + u0 + uu];
        smem[OFF_BZ  + uu] = bih[1 * 256 + u0 + uu] + bhh[1 * 256 + u0 + uu];
        smem[OFF_BIN + uu] = bih[2 * 256 + u0 + uu];
        smem[OFF_BHN + uu] = bhh[2 * 256 + u0 + uu];
    }
    // prime x buffers: (pair0,t0)->slot[0][0], (pair1,t0)->slot[1][0], (pair0,t1)->slot[0][1]
    for (int e = tid; e < 768; e += THREADS) {
        int buf = e >> 8;                 // 0..2
        int off = e & 255;
        int bb  = off >> 7;
        int k   = off & 127;
        int pr  = (buf == 1) ? 1 : 0;
        int par = (buf == 2) ? 1 : 0;
        int tt  = (buf == 2) ? 1 : 0;
        smem[OFF_X + (pr * 2 + par) * 256 + off] =
            x[((size_t)(b0 + pr * 2 + bb) * T_ + tt) * I_ + k];
    }

    // ---- one-time: W_hh into REGISTERS ----
    ull wh[48];
    #pragma unroll
    for (int g = 0; g < 3; ++g) {
        const float* row = Whh + (size_t)(g * 256 + u0 + u) * H_ + kw;
        #pragma unroll
        for (int j = 0; j < 16; ++j) {
            float2 v = *reinterpret_cast<const float2*>(row + 2 * j);
            wh[g * 16 + j] = packf2(v.x, v.y);
        }
    }
    __syncthreads();

    const float* wx0 = smem + OFF_WX + (0 * 32 + u) * WXSTRIDE;
    const float* wx1 = smem + OFF_WX + (1 * 32 + u) * WXSTRIDE;
    const float* wx2 = smem + OFF_WX + (2 * 32 + u) * WXSTRIDE;

    // prologue: PX for (pair0, t=0)
    if (wid >= 2 && wid < 6)
        xgemm_pair(smem, wx0, wx1, wx2, wid - 2, u, 0, 0);

    unsigned* flagBase = &g_flagsP[grp * 16];   // [pair]*8

    for (int s = 0; s < 2 * T_; ++s) {
        const int P = s & 1;
        const int t = s >> 1;
        __syncthreads();   // top: previous phase-2 writes visible (incl. cp.async post-wait)

        // ---- phase 1: h-GEMM (pair P, time t) on all 8 warps ----
        if (t > 0) {
            ull acc[6];
            #pragma unroll
            for (int i = 0; i < 6; ++i) acc[i] = 0ull;
            const float* hq = smem + OFF_H + P * 512;
            #pragma unroll
            for (int jj = 0; jj < 8; ++jj) {
                const int k = kw + 4 * jj;
                ulonglong2 h0 = *reinterpret_cast<const ulonglong2*>(hq + k);
                ulonglong2 h1 = *reinterpret_cast<const ulonglong2*>(hq + 256 + k);
                #pragma unroll
                for (int g = 0; g < 3; ++g) {
                    const ull wa = wh[g * 16 + 2 * jj];
                    const ull wb = wh[g * 16 + 2 * jj + 1];
                    FFMA2(acc[g * 2 + 0], wa, h0.x); FFMA2(acc[g * 2 + 0], wb, h0.y);
                    FFMA2(acc[g * 2 + 1], wa, h1.x); FFMA2(acc[g * 2 + 1], wb, h1.y);
                }
            }
            float* ph = smem + OFF_PH;
            #pragma unroll
            for (int g = 0; g < 3; ++g)
                #pragma unroll
                for (int b = 0; b < 2; ++b)
                    ph[((g * 2 + b) * 8 + wid) * 32 + u] = psum(acc[g * 2 + b]);
        }
        __syncthreads();   // phase 1 -> phase 2

        const int tn = t + P;          // time of next half-step (pair P^1)

        if (wid < 2) {
            // ---- combine (pair P, time t): warp = batch-in-pair, lane = unit ----
            const int b = wid, uu = u;
            const float* px = smem + OFF_PX + P * 768;
            float sx0 = 0.f, sx1 = 0.f, sx2 = 0.f;
            #pragma unroll
            for (int c = 0; c < 4; ++c) {
                sx0 += px[((0 * 2 + b) * 4 + c) * 32 + uu];
                sx1 += px[((1 * 2 + b) * 4 + c) * 32 + uu];
                sx2 += px[((2 * 2 + b) * 4 + c) * 32 + uu];
            }
            float sh0 = 0.f, sh1 = 0.f, sh2 = 0.f, hprev = 0.f;
            if (t > 0) {
                const float* ph = smem + OFF_PH;
                #pragma unroll
                for (int c = 0; c < 8; ++c) {
                    sh0 += ph[((0 * 2 + b) * 8 + c) * 32 + uu];
                    sh1 += ph[((1 * 2 + b) * 8 + c) * 32 + uu];
                    sh2 += ph[((2 * 2 + b) * 8 + c) * 32 + uu];
                }
                hprev = smem[OFF_H + P * 512 + b * 256 + u0 + uu];
            }
            const float pre_r = sx0 + sh0 + smem[OFF_BR + uu];
            const float pre_z = sx1 + sh1 + smem[OFF_BZ + uu];
            const float r = __fdividef(1.f, 1.f + __expf(-pre_r));
            const float z = __fdividef(1.f, 1.f + __expf(-pre_z));
            const float v = (sx2 + smem[OFF_BIN + uu]) + r * (sh2 + smem[OFF_BHN + uu]);
            const float nn = 1.f - __fdividef(2.f, __expf(2.f * v) + 1.f);   // tanh(v)
            const float hnew = (1.f - z) * nn + z * hprev;

            hid[((size_t)(b0 + P * 2 + b) * T_ + t) * H_ + u0 + uu] = hnew;

            __syncwarp();
            if (uu == 0)
                red_release_add(flagBase + P * 8, 1u);   // 16 publishes per (pair,t)
        } else if (wid < 6) {
            // ---- x-pipeline for next half-step (pair P^1) ----
            asm volatile("cp.async.wait_group 0;" ::: "memory");   // retire copy issued last half-step
            if (tn + 1 < T_) {
                const int idx = (wid - 2) * 32 + u;     // 0..127, 2 floats each
                const int bb  = idx >> 6;
                const int kk  = (idx & 63) * 2;
                uint32_t dst = sbase + (OFF_X + ((P ^ 1) * 2 + ((tn + 1) & 1)) * 256
                                        + bb * 128 + kk) * 4;
                const float* src = x + ((size_t)(b0 + (P ^ 1) * 2 + bb) * T_ + (tn + 1)) * I_ + kk;
                asm volatile("cp.async.ca.shared.global [%0], [%1], 8;" :: "r"(dst), "l"(src));
                asm volatile("cp.async.commit_group;" ::: "memory");
            }
            if (tn < T_)
                xgemm_pair(smem, wx0, wx1, wx2, wid - 2, u, P ^ 1, tn);
        } else {
            // ---- poll + load h_{tn-1} for pair P^1 (warp = batch-in-pair) ----
            if (tn > 0 && tn < T_) {
                const unsigned* fp = flagBase + (P ^ 1) * 8;
                const unsigned tgt = 16u * (unsigned)tn;
                while (ld_acquire(fp) < tgt) { }
                const int b  = wid - 6;
                const float* src = &hid[((size_t)(b0 + (P ^ 1) * 2 + b) * T_ + (tn - 1)) * H_];
                float4 v0 = *reinterpret_cast<const float4*>(src + u * 4);
                float4 v1 = *reinterpret_cast<const float4*>(src + 128 + u * 4);
                *reinterpret_cast<float4*>(&smem[OFF_H + (P ^ 1) * 512 + b * 256 + u * 4]) = v0;
                *reinterpret_cast<float4*>(&smem[OFF_H + (P ^ 1) * 512 + b * 256 + 128 + u * 4]) = v1;
            }
        }
    }
}

// outputs[b,t] = hiddens[b,t,:] . W_o + b_o ; resets flags for graph replay
__global__ void gru_out_kernel(const float* __restrict__ Wo,
                               const float* __restrict__ bo,
                               float* __restrict__ outbuf)
{
    if (blockIdx.x == 0) {
        for (int i = threadIdx.x; i < NFLAGW; i += blockDim.x)
            g_flagsP[i] = 0u;
    }

    int gw   = (int)((blockIdx.x * blockDim.x + threadIdx.x) >> 5);
    int lane = threadIdx.x & 31;
    if (gw >= B_ * T_) return;

    const float* hrow = outbuf + (size_t)B_ * T_ + (size_t)gw * H_;
    float s = 0.f;
    #pragma unroll
    for (int c = 0; c < 8; ++c) {
        int k = c * 32 + lane;
        s += hrow[k] * __ldg(&Wo[k]);
    }
    #pragma unroll
    for (int off = 16; off; off >>= 1)
        s += __shfl_xor_sync(0xffffffffu, s, off);
    if (lane == 0) outbuf[gw] = s + __ldg(&bo[0]);
}

extern "C" void kernel_launch(void* const* d_in, const int* in_sizes, int n_in,
                              void* d_out, int out_size)
{
    const float* x   = (const float*)d_in[0];
    const float* Wih = (const float*)d_in[1];
    const float* Whh = (const float*)d_in[2];
    const float* bih = (const float*)d_in[3];
    const float* bhh = (const float*)d_in[4];
    const float* Wo  = (const float*)d_in[5];
    const float* bo  = (const float*)d_in[6];
    float* out = (float*)d_out;

    cudaFuncSetAttribute(gru_scan_kernel,
                         cudaFuncAttributeMaxDynamicSharedMemorySize, SMEM_BYTES);

    gru_scan_kernel<<<NG * NS, THREADS, SMEM_BYTES>>>(x, Wih, Whh, bih, bhh, out);
    gru_out_kernel<<<(B_ * T_ * 32) / 256, 256>>>(Wo, bo, out);
}

// round 8
// speedup vs baseline: 2.4464x; 1.6649x over previous
#include <cuda_runtime.h>
#include <math.h>
#include <cstdint>

#define B_  64
#define T_  2048
#define I_  128
#define H_  256

#define NG 16      // batch groups
#define NS 8       // hidden slices per group
#define NB 4       // batches per group
#define NU 32      // hidden units per slice
#define THREADS 256

#define WXSTRIDE 132   // %32==4 -> conflict-free LDS.128 weight rows

// ---- SMEM layout (float offsets) ----
#define OFF_WX   0
#define SZ_WX    (3*32*WXSTRIDE)           // 12672
#define OFF_BR   (OFF_WX + SZ_WX)
#define OFF_BZ   (OFF_BR + 32)
#define OFF_BIN  (OFF_BZ + 32)
#define OFF_BHN  (OFF_BIN + 32)
#define OFF_X    (OFF_BHN + 32)            // 2 x [b][128] = 1024
#define OFF_H    (OFF_X + 1024)            // 2 x [b][256] = 2048
#define OFF_PX   (OFF_H + 2048)            // 2 x [g][b][chunk4][u] = 3072
#define OFF_PH   (OFF_PX + 3072)           // [g][b][chunk8][u] = 3072
#define SMEM_FLOATS (OFF_PH + 3072)
#define SMEM_BYTES  (SMEM_FLOATS * 4)      // ~88 KB

typedef unsigned long long ull;

// Self-validating h exchange: [grp][parity][b][unit] of packed {tag:32 | h:32}.
// tag = t+1 means "h_t". Cleared by out kernel each launch (graph-replay safe).
#define EXCH_WORDS (NG * 2 * NB * 256)     // 32768 u64 = 256 KB
__device__ ull g_exch[EXCH_WORDS];

__device__ __forceinline__ uint32_t smem_u32(const void* p) {
    uint32_t a;
    asm("{ .reg .u64 t; cvta.to.shared.u64 t, %1; cvt.u32.u64 %0, t; }" : "=r"(a) : "l"(p));
    return a;
}
#define FFMA2(d, a, b) \
    asm volatile("fma.rn.f32x2 %0, %1, %2, %0;" : "+l"(d) : "l"(a), "l"(b))

__device__ __forceinline__ float psum(ull v) {
    unsigned lo, hi;
    asm("mov.b64 {%0,%1}, %2;" : "=r"(lo), "=r"(hi) : "l"(v));
    return __uint_as_float(lo) + __uint_as_float(hi);
}
__device__ __forceinline__ ull packf2(float a, float b) {
    ull w;
    asm("mov.b64 %0, {%1,%2};" : "=l"(w) : "r"(__float_as_uint(a)), "r"(__float_as_uint(b)));
    return w;
}
__device__ __forceinline__ void st_relaxed_u64(ull* p, ull v) {
    asm volatile("st.relaxed.gpu.global.u64 [%0], %1;" :: "l"(p), "l"(v) : "memory");
}
__device__ __forceinline__ void ld_relaxed_v2u64(const ull* p, ull& a, ull& b) {
    asm volatile("ld.relaxed.gpu.global.v2.u64 {%0,%1}, [%2];"
                 : "=l"(a), "=l"(b) : "l"(p) : "memory");
}

__global__ void __launch_bounds__(THREADS, 1)
gru_scan_kernel(const float* __restrict__ x,
                const float* __restrict__ Wih,
                const float* __restrict__ Whh,
                const float* __restrict__ bih,
                const float* __restrict__ bhh,
                float* __restrict__ outbuf)
{
    extern __shared__ float smem[];
    const int tid = threadIdx.x;
    const int cta = blockIdx.x;
    const int grp = cta >> 3;
    const int slc = cta & 7;
    const int b0  = grp * NB;
    const int u0  = slc * NU;
    const uint32_t sbase = smem_u32(smem);

    float* hid = outbuf + (size_t)B_ * T_;   // hiddens [B][T][H]

    const int wid = tid >> 5;
    const int u   = tid & 31;
    const int kw  = wid * 32;                // this warp's K-chunk of W_hh

    // ---- one-time: W_ih slice into SMEM [g][u][k] (stride WXSTRIDE) ----
    for (int rk = tid; rk < 96 * 128; rk += THREADS) {
        int row = rk >> 7;
        int k   = rk & 127;
        int g   = row >> 5;
        int uu  = row & 31;
        smem[OFF_WX + (g * 32 + uu) * WXSTRIDE + k] =
            Wih[(size_t)(g * 256 + u0 + uu) * I_ + k];
    }
    if (tid < 32) {
        int uu = tid;
        smem[OFF_BR  + uu] = bih[0 * 256 + u0 + uu] + bhh[0 * 256 + u0 + uu];
        smem[OFF_BZ  + uu] = bih[1 * 256 + u0 + uu] + bhh[1 * 256 + u0 + uu];
        smem[OFF_BIN + uu] = bih[2 * 256 + u0 + uu];
        smem[OFF_BHN + uu] = bhh[2 * 256 + u0 + uu];
    }
    // preload x_0 into buffer 0: layout [b][k]
    for (int e = tid; e < 512; e += THREADS) {
        int b = e >> 7, k = e & 127;
        smem[OFF_X + e] = x[((size_t)(b0 + b) * T_ + 0) * I_ + k];
    }

    // ---- one-time: W_hh into REGISTERS ----
    ull wh[48];
    #pragma unroll
    for (int g = 0; g < 3; ++g) {
        const float* row = Whh + (size_t)(g * 256 + u0 + u) * H_ + kw;
        #pragma unroll
        for (int j = 0; j < 16; ++j) {
            float2 v = *reinterpret_cast<const float2*>(row + 2 * j);
            wh[g * 16 + j] = packf2(v.x, v.y);
        }
    }
    __syncthreads();

    // per-lane x-weight row bases (gates)
    const float* wx0 = smem + OFF_WX + (0 * 32 + u) * WXSTRIDE;
    const float* wx1 = smem + OFF_WX + (1 * 32 + u) * WXSTRIDE;
    const float* wx2 = smem + OFF_WX + (2 * 32 + u) * WXSTRIDE;

    for (int t = 0; t < T_; ++t) {
        const int p = t & 1;
        const int q = p ^ 1;

        if (wid < 4) {
            // ---- prefetch x_{t+1} ----
            if (t + 1 < T_) {
                int b = wid, c = u;
                uint32_t dst = sbase + (OFF_X + q * 512 + b * 128 + c * 4) * 4;
                const float* src = x + ((size_t)(b0 + b) * T_ + (t + 1)) * I_ + c * 4;
                asm volatile("cp.async.cg.shared.global [%0], [%1], 16;" :: "r"(dst), "l"(src));
                asm volatile("cp.async.commit_group;" ::: "memory");
            }
            // ---- x-GEMM: warp covers k in [wid*32, wid*32+32) ----
            ull acc[12];
            #pragma unroll
            for (int i = 0; i < 12; ++i) acc[i] = 0ull;

            const float* xq = smem + OFF_X + p * 512;
            const int kx = wid * 32;
            #pragma unroll
            for (int j = 0; j < 8; ++j) {
                const int k = kx + 4 * j;
                ulonglong2 xv0 = *reinterpret_cast<const ulonglong2*>(xq + 0 * 128 + k);
                ulonglong2 xv1 = *reinterpret_cast<const ulonglong2*>(xq + 1 * 128 + k);
                ulonglong2 xv2 = *reinterpret_cast<const ulonglong2*>(xq + 2 * 128 + k);
                ulonglong2 xv3 = *reinterpret_cast<const ulonglong2*>(xq + 3 * 128 + k);
                ulonglong2 w0 = *reinterpret_cast<const ulonglong2*>(wx0 + k);
                ulonglong2 w1 = *reinterpret_cast<const ulonglong2*>(wx1 + k);
                ulonglong2 w2 = *reinterpret_cast<const ulonglong2*>(wx2 + k);
                FFMA2(acc[0], w0.x, xv0.x); FFMA2(acc[0], w0.y, xv0.y);
                FFMA2(acc[1], w0.x, xv1.x); FFMA2(acc[1], w0.y, xv1.y);
                FFMA2(acc[2], w0.x, xv2.x); FFMA2(acc[2], w0.y, xv2.y);
                FFMA2(acc[3], w0.x, xv3.x); FFMA2(acc[3], w0.y, xv3.y);
                FFMA2(acc[4], w1.x, xv0.x); FFMA2(acc[4], w1.y, xv0.y);
                FFMA2(acc[5], w1.x, xv1.x); FFMA2(acc[5], w1.y, xv1.y);
                FFMA2(acc[6], w1.x, xv2.x); FFMA2(acc[6], w1.y, xv2.y);
                FFMA2(acc[7], w1.x, xv3.x); FFMA2(acc[7], w1.y, xv3.y);
                FFMA2(acc[8], w2.x, xv0.x); FFMA2(acc[8], w2.y, xv0.y);
                FFMA2(acc[9], w2.x, xv1.x); FFMA2(acc[9], w2.y, xv1.y);
                FFMA2(acc[10], w2.x, xv2.x); FFMA2(acc[10], w2.y, xv2.y);
                FFMA2(acc[11], w2.x, xv3.x); FFMA2(acc[11], w2.y, xv3.y);
            }
            float* px = smem + OFF_PX + p * 1536;
            #pragma unroll
            for (int g = 0; g < 3; ++g)
                #pragma unroll
                for (int b = 0; b < 4; ++b)
                    px[((g * 4 + b) * 4 + wid) * 32 + u] = psum(acc[g * 4 + b]);

            if (t + 1 < T_)
                asm volatile("cp.async.wait_group 0;" ::: "memory");
        } else {
            // ---- poll exchange words directly (warp = batch); data arrives with tags ----
            if (t > 0) {
                const int b = wid - 4;
                const ull* ep = g_exch + ((size_t)(grp * 2 + ((t - 1) & 1)) * NB + b) * 256;
                const unsigned tgt = (unsigned)t;
                ull v0, v1, v2, v3, v4, v5, v6, v7;
                for (;;) {
                    // instruction j reads a contiguous 512B span: index j*64 + u*2
                    ld_relaxed_v2u64(ep + 0 * 64 + u * 2, v0, v1);
                    ld_relaxed_v2u64(ep + 1 * 64 + u * 2, v2, v3);
                    ld_relaxed_v2u64(ep + 2 * 64 + u * 2, v4, v5);
                    ld_relaxed_v2u64(ep + 3 * 64 + u * 2, v6, v7);
                    bool ok = (unsigned)(v0 >> 32) == tgt && (unsigned)(v1 >> 32) == tgt &&
                              (unsigned)(v2 >> 32) == tgt && (unsigned)(v3 >> 32) == tgt &&
                              (unsigned)(v4 >> 32) == tgt && (unsigned)(v5 >> 32) == tgt &&
                              (unsigned)(v6 >> 32) == tgt && (unsigned)(v7 >> 32) == tgt;
                    if (__all_sync(0xffffffffu, ok)) break;
                }
                // h values already in registers -> SMEM
                float* hb = smem + OFF_H + p * 1024 + b * 256;
                *reinterpret_cast<float2*>(hb + 0 * 64 + u * 2) =
                    make_float2(__uint_as_float((unsigned)v0), __uint_as_float((unsigned)v1));
                *reinterpret_cast<float2*>(hb + 1 * 64 + u * 2) =
                    make_float2(__uint_as_float((unsigned)v2), __uint_as_float((unsigned)v3));
                *reinterpret_cast<float2*>(hb + 2 * 64 + u * 2) =
                    make_float2(__uint_as_float((unsigned)v4), __uint_as_float((unsigned)v5));
                *reinterpret_cast<float2*>(hb + 3 * 64 + u * 2) =
                    make_float2(__uint_as_float((unsigned)v6), __uint_as_float((unsigned)v7));
            }
        }
        __syncthreads();   // (A) sH ready; x_{t+1} landed

        // ---- h-GEMM: all 8 warps, weights from registers ----
        if (t > 0) {
            ull acc[12];
            #pragma unroll
            for (int i = 0; i < 12; ++i) acc[i] = 0ull;

            const float* hq = smem + OFF_H + p * 1024;
            #pragma unroll
            for (int jj = 0; jj < 8; ++jj) {
                const int k = kw + 4 * jj;
                ulonglong2 h0 = *reinterpret_cast<const ulonglong2*>(hq + 0 * 256 + k);
                ulonglong2 h1 = *reinterpret_cast<const ulonglong2*>(hq + 1 * 256 + k);
                ulonglong2 h2 = *reinterpret_cast<const ulonglong2*>(hq + 2 * 256 + k);
                ulonglong2 h3 = *reinterpret_cast<const ulonglong2*>(hq + 3 * 256 + k);
                #pragma unroll
                for (int g = 0; g < 3; ++g) {
                    const ull wa = wh[g * 16 + 2 * jj];
                    const ull wb = wh[g * 16 + 2 * jj + 1];
                    FFMA2(acc[g * 4 + 0], wa, h0.x); FFMA2(acc[g * 4 + 0], wb, h0.y);
                    FFMA2(acc[g * 4 + 1], wa, h1.x); FFMA2(acc[g * 4 + 1], wb, h1.y);
                    FFMA2(acc[g * 4 + 2], wa, h2.x); FFMA2(acc[g * 4 + 2], wb, h2.y);
                    FFMA2(acc[g * 4 + 3], wa, h3.x); FFMA2(acc[g * 4 + 3], wb, h3.y);
                }
            }
            float* ph = smem + OFF_PH;
            #pragma unroll
            for (int g = 0; g < 3; ++g)
                #pragma unroll
                for (int b = 0; b < 4; ++b)
                    ph[((g * 4 + b) * 8 + wid) * 32 + u] = psum(acc[g * 4 + b]);
        }
        __syncthreads();   // (B) sPh visible

        // ---- combine + self-validating publish: warps 0-3 (warp = batch, lane = unit) ----
        if (wid < 4) {
            const int bb = wid, uu = u;
            const float* px = smem + OFF_PX + p * 1536;
            float sx0 = 0.f, sx1 = 0.f, sx2 = 0.f;
            #pragma unroll
            for (int c = 0; c < 4; ++c) {
                sx0 += px[((0 * 4 + bb) * 4 + c) * 32 + uu];
                sx1 += px[((1 * 4 + bb) * 4 + c) * 32 + uu];
                sx2 += px[((2 * 4 + bb) * 4 + c) * 32 + uu];
            }
            float sh0 = 0.f, sh1 = 0.f, sh2 = 0.f, hprev = 0.f;
            if (t > 0) {
                const float* ph = smem + OFF_PH;
                #pragma unroll
                for (int c = 0; c < 8; ++c) {
                    sh0 += ph[((0 * 4 + bb) * 8 + c) * 32 + uu];
                    sh1 += ph[((1 * 4 + bb) * 8 + c) * 32 + uu];
                    sh2 += ph[((2 * 4 + bb) * 8 + c) * 32 + uu];
                }
                hprev = smem[OFF_H + p * 1024 + bb * 256 + u0 + uu];
            }
            const float pre_r = sx0 + sh0 + smem[OFF_BR + uu];
            const float pre_z = sx1 + sh1 + smem[OFF_BZ + uu];
            const float r = __fdividef(1.f, 1.f + __expf(-pre_r));
            const float z = __fdividef(1.f, 1.f + __expf(-pre_z));
            const float v = (sx2 + smem[OFF_BIN + uu]) + r * (sh2 + smem[OFF_BHN + uu]);
            const float nn = 1.f - __fdividef(2.f, __expf(2.f * v) + 1.f);   // tanh(v)
            const float hnew = (1.f - z) * nn + z * hprev;

            hid[((size_t)(b0 + bb) * T_ + t) * H_ + u0 + uu] = hnew;

            // publish {tag = t+1, h} as one atomic 8B word — no fence, no atomic RMW
            const ull pk = ((ull)(unsigned)(t + 1) << 32) | (ull)__float_as_uint(hnew);
            st_relaxed_u64(g_exch + ((size_t)(grp * 2 + p) * NB + bb) * 256 + u0 + uu, pk);
        }
        // no trailing syncthreads: parity double-buffering + tag backpressure make reuse safe
    }
}

// outputs[b,t] = hiddens[b,t,:] . W_o + b_o ; clears exchange tags for graph replay
__global__ void gru_out_kernel(const float* __restrict__ Wo,
                               const float* __restrict__ bo,
                               float* __restrict__ outbuf)
{
    if (blockIdx.x < 128)
        g_exch[(size_t)blockIdx.x * 256 + threadIdx.x] = 0ull;

    int gw   = (int)((blockIdx.x * blockDim.x + threadIdx.x) >> 5);
    int lane = threadIdx.x & 31;
    if (gw >= B_ * T_) return;

    const float* hrow = outbuf + (size_t)B_ * T_ + (size_t)gw * H_;
    float s = 0.f;
    #pragma unroll
    for (int c = 0; c < 8; ++c) {
        int k = c * 32 + lane;
        s += hrow[k] * __ldg(&Wo[k]);
    }
    #pragma unroll
    for (int off = 16; off; off >>= 1)
        s += __shfl_xor_sync(0xffffffffu, s, off);
    if (lane == 0) outbuf[gw] = s + __ldg(&bo[0]);
}

extern "C" void kernel_launch(void* const* d_in, const int* in_sizes, int n_in,
                              void* d_out, int out_size)
{
    const float* x   = (const float*)d_in[0];
    const float* Wih = (const float*)d_in[1];
    const float* Whh = (const float*)d_in[2];
    const float* bih = (const float*)d_in[3];
    const float* bhh = (const float*)d_in[4];
    const float* Wo  = (const float*)d_in[5];
    const float* bo  = (const float*)d_in[6];
    float* out = (float*)d_out;

    cudaFuncSetAttribute(gru_scan_kernel,
                         cudaFuncAttributeMaxDynamicSharedMemorySize, SMEM_BYTES);

    gru_scan_kernel<<<NG * NS, THREADS, SMEM_BYTES>>>(x, Wih, Whh, bih, bhh, out);
    gru_out_kernel<<<(B_ * T_ * 32) / 256, 256>>>(Wo, bo, out);
}